// round 1
// baseline (speedup 1.0000x reference)
#include <cuda_runtime.h>

#define BATCH 8
#define NSEQ  2048
#define DIM   256
#define NROWS (BATCH * NSEQ)          // 16384
#define NEGV  (-999999.0f)

// ---------------- scratch (device globals; no allocation allowed) ----------
__device__ float g_h[(size_t)NROWS * DIM];   // h = X @ W        (16.8 MB)
__device__ float g_asrc[NROWS];
__device__ float g_adst[NROWS];
__device__ float g_rowmax[NROWS];
__device__ float g_rowsum[NROWS];

__device__ __forceinline__ float fsigmoid(float x) {
    return __fdividef(1.0f, 1.0f + __expf(-x));
}

// ---------------- K1: h = X @ W   (NN GEMM, M=16384, N=256, K=256) ---------
__global__ __launch_bounds__(256) void k1_h_gemm(const float* __restrict__ X,
                                                 const float* __restrict__ W)
{
    __shared__ float As[16][65];   // [k][m]
    __shared__ float Bs[16][64];   // [k][n]
    const int t  = threadIdx.x;
    const int tx = t & 15, ty = t >> 4;
    const int m0 = blockIdx.y * 64, n0 = blockIdx.x * 64;
    float acc[4][4] = {};
    for (int k0 = 0; k0 < DIM; k0 += 16) {
        {   // A tile 64x16, transposed store
            int r = t >> 2, c4 = t & 3;
            float4 v = *(const float4*)(X + (size_t)(m0 + r) * DIM + k0 + c4 * 4);
            As[c4*4+0][r] = v.x; As[c4*4+1][r] = v.y;
            As[c4*4+2][r] = v.z; As[c4*4+3][r] = v.w;
        }
        {   // B tile 16x64
            int r = t >> 4, c4 = t & 15;
            *(float4*)&Bs[r][c4*4] = *(const float4*)(W + (size_t)(k0 + r) * DIM + n0 + c4 * 4);
        }
        __syncthreads();
        #pragma unroll
        for (int k = 0; k < 16; k++) {
            float a[4], bb[4];
            #pragma unroll
            for (int r = 0; r < 4; r++) a[r] = As[k][ty*4 + r];
            *(float4*)bb = *(float4*)&Bs[k][tx*4];
            #pragma unroll
            for (int r = 0; r < 4; r++)
                #pragma unroll
                for (int c = 0; c < 4; c++)
                    acc[r][c] = fmaf(a[r], bb[c], acc[r][c]);
        }
        __syncthreads();
    }
    #pragma unroll
    for (int r = 0; r < 4; r++) {
        float4 v = make_float4(acc[r][0], acc[r][1], acc[r][2], acc[r][3]);
        *(float4*)&g_h[(size_t)(m0 + ty*4 + r) * DIM + n0 + tx*4] = v;
    }
}

// ---------------- K2: a_src / a_dst  (two dots per row of h) ----------------
__global__ __launch_bounds__(256) void k2_coef(const float* __restrict__ Ws)
{
    const int r = blockIdx.x;
    const int t = threadIdx.x;
    float hv = g_h[(size_t)r * DIM + t];
    float ps = hv * Ws[t];
    float pd = hv * Ws[DIM + t];
    __shared__ float ss[8], sd[8];
    #pragma unroll
    for (int o = 16; o > 0; o >>= 1) {
        ps += __shfl_down_sync(0xffffffffu, ps, o);
        pd += __shfl_down_sync(0xffffffffu, pd, o);
    }
    if ((t & 31) == 0) { ss[t >> 5] = ps; sd[t >> 5] = pd; }
    __syncthreads();
    if (t == 0) {
        float a = 0.f, d = 0.f;
        #pragma unroll
        for (int w = 0; w < 8; w++) { a += ss[w]; d += sd[w]; }
        g_asrc[r] = a;
        g_adst[r] = d;
    }
}

// ---------------- K3: write I_A, compute per-row softmax max/sum ------------
__global__ __launch_bounds__(256) void k3_ia_stats(const int*   __restrict__ adj,
                                                   const float* __restrict__ bsv,
                                                   float*       __restrict__ outIA)
{
    const int i = blockIdx.x;
    const int b = blockIdx.y;
    const int t = threadIdx.x;
    const size_t rbase = ((size_t)b * NSEQ + i) * NSEQ;
    const float asrc = g_asrc[b * NSEQ + i];
    const float bs0  = bsv[0];

    float sc[8];
    float mx = -3.0e38f;
    #pragma unroll
    for (int p = 0; p < 8; p++) {
        int j = t + p * 256;
        int av = adj[rbase + j];
        float x = asrc + g_adst[b * NSEQ + j] + bs0;
        float attn = (j < i) ? fsigmoid(x) : 0.0f;
        float ia = ((j == i) ? 1.0f : 0.0f) - attn;
        outIA[rbase + j] = ia;                       // I_A_raw: NOT adj-masked
        float s = ((j <= i) && (av == 1)) ? ia : NEGV;
        sc[p] = s;
        mx = fmaxf(mx, s);
    }
    __shared__ float redm[8], reds[8];
    #pragma unroll
    for (int o = 16; o > 0; o >>= 1) mx = fmaxf(mx, __shfl_xor_sync(0xffffffffu, mx, o));
    if ((t & 31) == 0) redm[t >> 5] = mx;
    __syncthreads();
    float bm = redm[0];
    #pragma unroll
    for (int w = 1; w < 8; w++) bm = fmaxf(bm, redm[w]);

    float sum = 0.f;
    #pragma unroll
    for (int p = 0; p < 8; p++) sum += __expf(sc[p] - bm);   // all-NEG row -> exp(0)=1 each
    #pragma unroll
    for (int o = 16; o > 0; o >>= 1) sum += __shfl_xor_sync(0xffffffffu, sum, o);
    if ((t & 31) == 0) reds[t >> 5] = sum;
    __syncthreads();
    if (t == 0) {
        float s = 0.f;
        #pragma unroll
        for (int w = 0; w < 8; w++) s += reds[w];
        g_rowmax[b * NSEQ + i] = bm;
        g_rowsum[b * NSEQ + i] = s;
    }
}

// ---------------- K4: feat_out = P @ h + b (P recomputed per tile) ----------
#define BM4 64
#define BJ4 32
#define BN4 128
__global__ __launch_bounds__(256) void k4_pv(const int*   __restrict__ adj,
                                             const float* __restrict__ bias,
                                             const float* __restrict__ bsv,
                                             float*       __restrict__ outFO)
{
    __shared__ float Ps[BM4][BJ4 + 1];     // P tile [i][j]
    __shared__ float Hs[BJ4][BN4 + 4];     // h tile [j][d]
    __shared__ float s_asrc[BM4], s_m[BM4], s_inv[BM4], s_adst[BJ4];
    const int b  = blockIdx.z;
    const int i0 = blockIdx.y * BM4;
    const int n0 = blockIdx.x * BN4;
    const int t  = threadIdx.x;
    const int tx = t & 15, ty = t >> 4;

    if (t < BM4) {
        int r = b * NSEQ + i0 + t;
        s_asrc[t] = g_asrc[r];
        s_m[t]    = g_rowmax[r];
        s_inv[t]  = __fdividef(1.0f, g_rowsum[r]);
    }
    const float bs0 = bsv[0];
    float acc[4][8] = {};

    for (int j0 = 0; j0 < NSEQ; j0 += BJ4) {
        __syncthreads();                                   // protect smem reuse
        if (t < BJ4) s_adst[t] = g_adst[b * NSEQ + j0 + t];
        __syncthreads();
        // phase A: P tile (64x32)
        #pragma unroll
        for (int p = 0; p < 8; p++) {
            int idx = p * 256 + t;
            int ii = idx >> 5, jj = idx & 31;
            int i = i0 + ii, j = j0 + jj;
            int av = adj[((size_t)b * NSEQ + i) * NSEQ + j];
            float x = s_asrc[ii] + s_adst[jj] + bs0;
            float attn = (j < i) ? fsigmoid(x) : 0.0f;
            float ia = ((j == i) ? 1.0f : 0.0f) - attn;
            float s = ((j <= i) && (av == 1)) ? ia : NEGV;
            Ps[ii][jj] = __expf(s - s_m[ii]) * s_inv[ii];
        }
        // phase B: h tile (32x128)
        #pragma unroll
        for (int q = 0; q < 4; q++) {
            int r  = q * 8 + (t >> 5);
            int c4 = t & 31;
            *(float4*)&Hs[r][c4 * 4] =
                *(const float4*)(g_h + ((size_t)b * NSEQ + j0 + r) * DIM + n0 + c4 * 4);
        }
        __syncthreads();
        // FMA mainloop
        #pragma unroll
        for (int k = 0; k < BJ4; k++) {
            float a[4], bb[8];
            #pragma unroll
            for (int r = 0; r < 4; r++) a[r] = Ps[ty*4 + r][k];
            *(float4*)&bb[0] = *(float4*)&Hs[k][tx*8];
            *(float4*)&bb[4] = *(float4*)&Hs[k][tx*8 + 4];
            #pragma unroll
            for (int r = 0; r < 4; r++)
                #pragma unroll
                for (int c = 0; c < 8; c++)
                    acc[r][c] = fmaf(a[r], bb[c], acc[r][c]);
        }
    }
    #pragma unroll
    for (int r = 0; r < 4; r++) {
        int i = i0 + ty*4 + r;
        #pragma unroll
        for (int c = 0; c < 8; c += 4) {
            float4 v;
            v.x = acc[r][c+0] + bias[n0 + tx*8 + c + 0];
            v.y = acc[r][c+1] + bias[n0 + tx*8 + c + 1];
            v.z = acc[r][c+2] + bias[n0 + tx*8 + c + 2];
            v.w = acc[r][c+3] + bias[n0 + tx*8 + c + 3];
            *(float4*)&outFO[((size_t)b * NSEQ + i) * DIM + n0 + tx*8 + c] = v;
        }
    }
}

// ---------------- K5: gate GEMM (NT) + elu + blend, in-place on d_out -------
__global__ __launch_bounds__(256) void k5_gate(const float* __restrict__ X,
                                               const float* __restrict__ Hw,
                                               const float* __restrict__ Hb,
                                               float*       __restrict__ out)
{
    __shared__ float As[16][65];   // [k][m]
    __shared__ float Bs[16][65];   // [k][d]
    const int t  = threadIdx.x;
    const int tx = t & 15, ty = t >> 4;
    const int m0 = blockIdx.y * 64, n0 = blockIdx.x * 64;
    float acc[4][4] = {};
    for (int k0 = 0; k0 < DIM; k0 += 16) {
        {
            int r = t >> 2, c4 = t & 3;
            float4 v = *(const float4*)(X + (size_t)(m0 + r) * DIM + k0 + c4 * 4);
            As[c4*4+0][r] = v.x; As[c4*4+1][r] = v.y;
            As[c4*4+2][r] = v.z; As[c4*4+3][r] = v.w;
            float4 w = *(const float4*)(Hw + (size_t)(n0 + r) * DIM + k0 + c4 * 4);
            Bs[c4*4+0][r] = w.x; Bs[c4*4+1][r] = w.y;
            Bs[c4*4+2][r] = w.z; Bs[c4*4+3][r] = w.w;
        }
        __syncthreads();
        #pragma unroll
        for (int k = 0; k < 16; k++) {
            float a[4], bb[4];
            #pragma unroll
            for (int r = 0; r < 4; r++) a[r] = As[k][ty*4 + r];
            #pragma unroll
            for (int c = 0; c < 4; c++) bb[c] = Bs[k][tx*4 + c];
            #pragma unroll
            for (int r = 0; r < 4; r++)
                #pragma unroll
                for (int c = 0; c < 4; c++)
                    acc[r][c] = fmaf(a[r], bb[c], acc[r][c]);
        }
        __syncthreads();
    }
    #pragma unroll
    for (int r = 0; r < 4; r++) {
        int row = m0 + ty*4 + r;
        #pragma unroll
        for (int c = 0; c < 4; c++) {
            int col = n0 + tx*4 + c;
            size_t o = (size_t)row * DIM + col;
            float g  = fsigmoid(acc[r][c] + Hb[col]);
            float fo = out[o];
            float e  = (fo > 0.0f) ? fo : expm1f(fo);
            out[o] = g * e + (1.0f - g) * X[o];
        }
    }
}

// ---------------- launch ----------------------------------------------------
extern "C" void kernel_launch(void* const* d_in, const int* in_sizes, int n_in,
                              void* d_out, int out_size)
{
    const float* feat = (const float*)d_in[0];
    const int*   adj  = (const int*)  d_in[1];
    const float* W    = (const float*)d_in[2];
    const float* bvec = (const float*)d_in[3];
    const float* Ws   = (const float*)d_in[4];
    const float* bs   = (const float*)d_in[5];
    const float* Hw   = (const float*)d_in[6];
    const float* Hb   = (const float*)d_in[7];

    float* out   = (float*)d_out;                      // (B,N,256)
    float* outIA = out + (size_t)NROWS * DIM;          // (B,1,N,N)

    k1_h_gemm<<<dim3(DIM / 64, NROWS / 64), 256>>>(feat, W);
    k2_coef  <<<NROWS, 256>>>(Ws);
    k3_ia_stats<<<dim3(NSEQ, BATCH), 256>>>(adj, bs, outIA);
    k4_pv    <<<dim3(DIM / BN4, NSEQ / BM4, BATCH), 256>>>(adj, bvec, bs, out);
    k5_gate  <<<dim3(DIM / 64, NROWS / 64), 256>>>(feat, Hw, Hb, out);
}

// round 3
// speedup vs baseline: 2.4020x; 2.4020x over previous
#include <cuda_runtime.h>
#include <cuda_bf16.h>

#define BATCH 8
#define NSEQ  2048
#define DIM   256
#define NROWS (BATCH * NSEQ)          // 16384
#define NEGV  (-999999.0f)

// ---------------- scratch (device globals; no allocation allowed) ----------
__device__ float g_h[(size_t)NROWS * DIM];              // h = X @ W   (16.8 MB)
__device__ __nv_bfloat16 g_hT_hi[(size_t)NROWS * DIM];  // h^T split hi [b][d][j]
__device__ __nv_bfloat16 g_hT_lo[(size_t)NROWS * DIM];  // h^T split lo [b][d][j]
__device__ float g_asrc[NROWS];
__device__ float g_adst[NROWS];
__device__ float g_rowmax[NROWS];
__device__ float g_rowsum[NROWS];

__device__ __forceinline__ float fsigmoid(float x) {
    return __fdividef(1.0f, 1.0f + __expf(-x));
}

__device__ __forceinline__ unsigned smem_u32(const void* p) {
    unsigned a;
    asm("{ .reg .u64 t; cvta.to.shared.u64 t, %1; cvt.u32.u64 %0, t; }"
        : "=r"(a) : "l"(p));
    return a;
}

__device__ __forceinline__ void ldsm_x4(unsigned r[4], unsigned addr) {
    asm volatile("ldmatrix.sync.aligned.m8n8.x4.shared.b16 {%0,%1,%2,%3}, [%4];"
                 : "=r"(r[0]), "=r"(r[1]), "=r"(r[2]), "=r"(r[3]) : "r"(addr));
}

__device__ __forceinline__ void mma_bf16(float c[4], const unsigned a[4],
                                         unsigned b0, unsigned b1) {
    asm volatile("mma.sync.aligned.m16n8k16.row.col.f32.bf16.bf16.f32 "
                 "{%0,%1,%2,%3}, {%4,%5,%6,%7}, {%8,%9}, {%0,%1,%2,%3};"
                 : "+f"(c[0]), "+f"(c[1]), "+f"(c[2]), "+f"(c[3])
                 : "r"(a[0]), "r"(a[1]), "r"(a[2]), "r"(a[3]), "r"(b0), "r"(b1));
}

// ---------------- K1: h = X @ W   (NN GEMM, M=16384, N=256, K=256) ---------
__global__ __launch_bounds__(256) void k1_h_gemm(const float* __restrict__ X,
                                                 const float* __restrict__ W)
{
    __shared__ float As[16][65];   // [k][m]
    __shared__ float Bs[16][64];   // [k][n]
    const int t  = threadIdx.x;
    const int tx = t & 15, ty = t >> 4;
    const int m0 = blockIdx.y * 64, n0 = blockIdx.x * 64;
    float acc[4][4] = {};
    for (int k0 = 0; k0 < DIM; k0 += 16) {
        {
            int r = t >> 2, c4 = t & 3;
            float4 v = *(const float4*)(X + (size_t)(m0 + r) * DIM + k0 + c4 * 4);
            As[c4*4+0][r] = v.x; As[c4*4+1][r] = v.y;
            As[c4*4+2][r] = v.z; As[c4*4+3][r] = v.w;
        }
        {
            int r = t >> 4, c4 = t & 15;
            *(float4*)&Bs[r][c4*4] = *(const float4*)(W + (size_t)(k0 + r) * DIM + n0 + c4 * 4);
        }
        __syncthreads();
        #pragma unroll
        for (int k = 0; k < 16; k++) {
            float a[4], bb[4];
            #pragma unroll
            for (int r = 0; r < 4; r++) a[r] = As[k][ty*4 + r];
            *(float4*)bb = *(float4*)&Bs[k][tx*4];
            #pragma unroll
            for (int r = 0; r < 4; r++)
                #pragma unroll
                for (int c = 0; c < 4; c++)
                    acc[r][c] = fmaf(a[r], bb[c], acc[r][c]);
        }
        __syncthreads();
    }
    #pragma unroll
    for (int r = 0; r < 4; r++) {
        float4 v = make_float4(acc[r][0], acc[r][1], acc[r][2], acc[r][3]);
        *(float4*)&g_h[(size_t)(m0 + ty*4 + r) * DIM + n0 + tx*4] = v;
    }
}

// ---------------- K2: a_src / a_dst ------------------------------------------
__global__ __launch_bounds__(256) void k2_coef(const float* __restrict__ Ws)
{
    const int r = blockIdx.x;
    const int t = threadIdx.x;
    float hv = g_h[(size_t)r * DIM + t];
    float ps = hv * Ws[t];
    float pd = hv * Ws[DIM + t];
    __shared__ float ss[8], sd[8];
    #pragma unroll
    for (int o = 16; o > 0; o >>= 1) {
        ps += __shfl_down_sync(0xffffffffu, ps, o);
        pd += __shfl_down_sync(0xffffffffu, pd, o);
    }
    if ((t & 31) == 0) { ss[t >> 5] = ps; sd[t >> 5] = pd; }
    __syncthreads();
    if (t == 0) {
        float a = 0.f, d = 0.f;
        #pragma unroll
        for (int w = 0; w < 8; w++) { a += ss[w]; d += sd[w]; }
        g_asrc[r] = a;
        g_adst[r] = d;
    }
}

// ---------------- K2b: transpose + bf16 split  h -> hT_hi/lo [b][d][j] ------
__global__ __launch_bounds__(256) void k2b_split()
{
    __shared__ float tile[32][33];
    const int b = blockIdx.z, j0 = blockIdx.x * 32, d0 = blockIdx.y * 32;
    const int c = threadIdx.x & 31, r0 = threadIdx.x >> 5;
    #pragma unroll
    for (int k = 0; k < 4; k++) {
        int r = r0 + k * 8;
        tile[r][c] = g_h[((size_t)(b * NSEQ + j0 + r)) * DIM + d0 + c];
    }
    __syncthreads();
    #pragma unroll
    for (int k = 0; k < 4; k++) {
        int r = r0 + k * 8;           // d offset within tile
        float v = tile[c][r];
        __nv_bfloat16 hb = __float2bfloat16_rn(v);
        float hf = __bfloat162float(hb);
        __nv_bfloat16 lb = __float2bfloat16_rn(v - hf);
        size_t o = ((size_t)(b * DIM + d0 + r)) * NSEQ + j0 + c;
        g_hT_hi[o] = hb;
        g_hT_lo[o] = lb;
    }
}

// ---------------- K3: write I_A, compute per-row softmax max/sum ------------
__global__ __launch_bounds__(256) void k3_ia_stats(const int*   __restrict__ adj,
                                                   const float* __restrict__ bsv,
                                                   float*       __restrict__ outIA)
{
    const int i = blockIdx.x;
    const int b = blockIdx.y;
    const int t = threadIdx.x;
    const size_t rbase = ((size_t)b * NSEQ + i) * NSEQ;
    const float asrc = g_asrc[b * NSEQ + i];
    const float bs0  = bsv[0];

    float sc[8];
    float mx = -3.0e38f;
    #pragma unroll
    for (int p = 0; p < 8; p++) {
        int j = t + p * 256;
        int av = adj[rbase + j];
        float x = asrc + g_adst[b * NSEQ + j] + bs0;
        float attn = (j < i) ? fsigmoid(x) : 0.0f;
        float ia = ((j == i) ? 1.0f : 0.0f) - attn;
        outIA[rbase + j] = ia;                       // I_A_raw: NOT adj-masked
        float s = ((j <= i) && (av == 1)) ? ia : NEGV;
        sc[p] = s;
        mx = fmaxf(mx, s);
    }
    __shared__ float redm[8], reds[8];
    #pragma unroll
    for (int o = 16; o > 0; o >>= 1) mx = fmaxf(mx, __shfl_xor_sync(0xffffffffu, mx, o));
    if ((t & 31) == 0) redm[t >> 5] = mx;
    __syncthreads();
    float bm = redm[0];
    #pragma unroll
    for (int w = 1; w < 8; w++) bm = fmaxf(bm, redm[w]);

    float sum = 0.f;
    #pragma unroll
    for (int p = 0; p < 8; p++) sum += __expf(sc[p] - bm);
    #pragma unroll
    for (int o = 16; o > 0; o >>= 1) sum += __shfl_xor_sync(0xffffffffu, sum, o);
    if ((t & 31) == 0) reds[t >> 5] = sum;
    __syncthreads();
    if (t == 0) {
        float s = 0.f;
        #pragma unroll
        for (int w = 0; w < 8; w++) s += reds[w];
        g_rowmax[b * NSEQ + i] = bm;
        g_rowsum[b * NSEQ + i] = s;
    }
}

// ---------------- K4: feat_out = P @ h + b via mma.sync bf16 hi/lo split ----
// CTA: M=64 (i), N=256 (d), K-chunks of 64 (j). 8 warps = 2(m) x 4(n),
// warp tile m32 x n64. SMEM rows pitched 144B (conflict-free ldmatrix).
#define KCH    64
#define PITCHB 144
__global__ __launch_bounds__(256, 2) void k4_mma(const int*   __restrict__ adj,
                                                 const float* __restrict__ bias,
                                                 const float* __restrict__ bsv,
                                                 float*       __restrict__ outFO)
{
    extern __shared__ char sm[];
    // layout: A_hi[64][144B] @0 (9216), A_lo @9216, B_hi[256][144B] @18432 (36864), B_lo @55296
    __shared__ float s_asrc[64], s_m[64], s_inv[64], s_adst[KCH];

    const int t    = threadIdx.x;
    const int lane = t & 31;
    const int wid  = t >> 5;
    const int wm   = wid & 1;          // m warp (0/1) -> rows 32*wm
    const int wn   = wid >> 1;         // n warp (0..3) -> cols 64*wn
    const int b    = blockIdx.y;
    const int i0   = blockIdx.x * 64;

    char* sA_hi = sm;
    char* sA_lo = sm + 9216;
    char* sB_hi = sm + 18432;
    char* sB_lo = sm + 55296;

    if (t < 64) {
        int r = b * NSEQ + i0 + t;
        s_asrc[t] = g_asrc[r];
        s_m[t]    = g_rowmax[r];
        s_inv[t]  = __fdividef(1.0f, g_rowsum[r]);
    }
    const float bs0 = bsv[0];

    // per-lane ldmatrix base offsets (row = l&15, halftile col = (l>>4)*16B)
    const unsigned lrow = (lane & 15);
    const unsigned lcol = (lane >> 4) << 4;
    const unsigned aBase0 = smem_u32(sA_hi) + (wm * 32 + lrow) * PITCHB + lcol;
    const unsigned bBase0 = smem_u32(sB_hi) + (wn * 64 + lrow) * PITCHB + lcol;

    // P-compute mapping: 4 threads per row, 16 j each
    const int pii = t >> 2;
    const int pjq = (t & 3) << 4;

    float acc[2][8][4] = {};

    for (int c = 0; c < NSEQ / KCH; c++) {
        const int j0 = c * KCH;
        __syncthreads();                 // previous chunk's mma done
        if (t < KCH) s_adst[t] = g_adst[b * NSEQ + j0 + t];
        __syncthreads();

        // ---- P tile 64x64 -> bf16 hi/lo into sA ----
        {
            const int i = i0 + pii;
            const float asrc = s_asrc[pii], m = s_m[pii], inv = s_inv[pii];
            const int* arow = adj + ((size_t)(b * NSEQ + i)) * NSEQ + j0 + pjq;
            #pragma unroll
            for (int half = 0; half < 2; half++) {
                int4 a0 = ((const int4*)arow)[half * 2 + 0];
                int4 a1 = ((const int4*)arow)[half * 2 + 1];
                int av[8] = {a0.x, a0.y, a0.z, a0.w, a1.x, a1.y, a1.z, a1.w};
                union { __nv_bfloat16 h[8]; uint4 v; } Uh, Ul;
                #pragma unroll
                for (int e = 0; e < 8; e++) {
                    const int jl = pjq + half * 8 + e;
                    const int j  = j0 + jl;
                    float x = asrc + s_adst[jl] + bs0;
                    float attn = (j < i) ? fsigmoid(x) : 0.0f;
                    float ia = ((j == i) ? 1.0f : 0.0f) - attn;
                    float sc = ((j <= i) && (av[e] == 1)) ? ia : NEGV;
                    float pv = __expf(sc - m) * inv;
                    __nv_bfloat16 hb = __float2bfloat16_rn(pv);
                    Uh.h[e] = hb;
                    Ul.h[e] = __float2bfloat16_rn(pv - __bfloat162float(hb));
                }
                const unsigned off = pii * PITCHB + (pjq + half * 8) * 2;
                *(uint4*)(sA_hi + off) = Uh.v;
                *(uint4*)(sA_lo + off) = Ul.v;
            }
        }

        // ---- B tile: h^T 256 x 64 hi/lo ----
        #pragma unroll
        for (int q = 0; q < 8; q++) {
            const int idx = q * 256 + t;
            const int d = idx >> 3, seg = idx & 7;
            const size_t go = ((size_t)(b * DIM + d)) * NSEQ + j0 + seg * 8;
            const unsigned off = d * PITCHB + seg * 16;
            *(uint4*)(sB_hi + off) = *(const uint4*)(g_hT_hi + go);
            *(uint4*)(sB_lo + off) = *(const uint4*)(g_hT_lo + go);
        }
        __syncthreads();

        // ---- mma mainloop over 4 k-steps ----
        #pragma unroll
        for (int ks = 0; ks < 4; ks++) {
            unsigned ah[2][4], al[2][4];
            #pragma unroll
            for (int mt = 0; mt < 2; mt++) {
                ldsm_x4(ah[mt], aBase0 + mt * 16 * PITCHB + ks * 32);
                ldsm_x4(al[mt], aBase0 + 9216u + mt * 16 * PITCHB + ks * 32);
            }
            #pragma unroll
            for (int np = 0; np < 4; np++) {
                unsigned bh[4], bl[4];
                ldsm_x4(bh, bBase0 + np * 16 * PITCHB + ks * 32);
                ldsm_x4(bl, bBase0 + 36864u + np * 16 * PITCHB + ks * 32);
                #pragma unroll
                for (int mt = 0; mt < 2; mt++) {
                    // nf even = np*2, odd = np*2+1
                    mma_bf16(acc[mt][np*2+0], ah[mt], bh[0], bh[2]);   // hi*hi
                    mma_bf16(acc[mt][np*2+1], ah[mt], bh[1], bh[3]);
                    mma_bf16(acc[mt][np*2+0], ah[mt], bl[0], bl[2]);   // hi*lo
                    mma_bf16(acc[mt][np*2+1], ah[mt], bl[1], bl[3]);
                    mma_bf16(acc[mt][np*2+0], al[mt], bh[0], bh[2]);   // lo*hi
                    mma_bf16(acc[mt][np*2+1], al[mt], bh[1], bh[3]);
                }
            }
        }
    }

    // ---- epilogue: accum + bias -> outFO ----
    #pragma unroll
    for (int mt = 0; mt < 2; mt++) {
        const int row0 = i0 + wm * 32 + mt * 16 + (lane >> 2);
        #pragma unroll
        for (int nf = 0; nf < 8; nf++) {
            const int col = wn * 64 + nf * 8 + (lane & 3) * 2;
            const float b0 = bias[col], b1 = bias[col + 1];
            float2 v0 = make_float2(acc[mt][nf][0] + b0, acc[mt][nf][1] + b1);
            float2 v1 = make_float2(acc[mt][nf][2] + b0, acc[mt][nf][3] + b1);
            *(float2*)(outFO + ((size_t)(b * NSEQ + row0)) * DIM + col) = v0;
            *(float2*)(outFO + ((size_t)(b * NSEQ + row0 + 8)) * DIM + col) = v1;
        }
    }
}

// ---------------- K5: gate GEMM (NT) + elu + blend, in-place on d_out -------
__global__ __launch_bounds__(256) void k5_gate(const float* __restrict__ X,
                                               const float* __restrict__ Hw,
                                               const float* __restrict__ Hb,
                                               float*       __restrict__ out)
{
    __shared__ float As[16][65];
    __shared__ float Bs[16][65];
    const int t  = threadIdx.x;
    const int tx = t & 15, ty = t >> 4;
    const int m0 = blockIdx.y * 64, n0 = blockIdx.x * 64;
    float acc[4][4] = {};
    for (int k0 = 0; k0 < DIM; k0 += 16) {
        {
            int r = t >> 2, c4 = t & 3;
            float4 v = *(const float4*)(X + (size_t)(m0 + r) * DIM + k0 + c4 * 4);
            As[c4*4+0][r] = v.x; As[c4*4+1][r] = v.y;
            As[c4*4+2][r] = v.z; As[c4*4+3][r] = v.w;
            float4 w = *(const float4*)(Hw + (size_t)(n0 + r) * DIM + k0 + c4 * 4);
            Bs[c4*4+0][r] = w.x; Bs[c4*4+1][r] = w.y;
            Bs[c4*4+2][r] = w.z; Bs[c4*4+3][r] = w.w;
        }
        __syncthreads();
        #pragma unroll
        for (int k = 0; k < 16; k++) {
            float a[4], bb[4];
            #pragma unroll
            for (int r = 0; r < 4; r++) a[r] = As[k][ty*4 + r];
            #pragma unroll
            for (int c = 0; c < 4; c++) bb[c] = Bs[k][tx*4 + c];
            #pragma unroll
            for (int r = 0; r < 4; r++)
                #pragma unroll
                for (int c = 0; c < 4; c++)
                    acc[r][c] = fmaf(a[r], bb[c], acc[r][c]);
        }
        __syncthreads();
    }
    #pragma unroll
    for (int r = 0; r < 4; r++) {
        int row = m0 + ty*4 + r;
        #pragma unroll
        for (int c = 0; c < 4; c++) {
            int col = n0 + tx*4 + c;
            size_t o = (size_t)row * DIM + col;
            float g  = fsigmoid(acc[r][c] + Hb[col]);
            float fo = out[o];
            float e  = (fo > 0.0f) ? fo : expm1f(fo);
            out[o] = g * e + (1.0f - g) * X[o];
        }
    }
}

// ---------------- launch ----------------------------------------------------
extern "C" void kernel_launch(void* const* d_in, const int* in_sizes, int n_in,
                              void* d_out, int out_size)
{
    const float* feat = (const float*)d_in[0];
    const int*   adj  = (const int*)  d_in[1];
    const float* W    = (const float*)d_in[2];
    const float* bvec = (const float*)d_in[3];
    const float* Ws   = (const float*)d_in[4];
    const float* bs   = (const float*)d_in[5];
    const float* Hw   = (const float*)d_in[6];
    const float* Hb   = (const float*)d_in[7];

    float* out   = (float*)d_out;                      // (B,N,256)
    float* outIA = out + (size_t)NROWS * DIM;          // (B,1,N,N)

    cudaFuncSetAttribute(k4_mma, cudaFuncAttributeMaxDynamicSharedMemorySize, 92160);

    k1_h_gemm<<<dim3(DIM / 64, NROWS / 64), 256>>>(feat, W);
    k2_coef  <<<NROWS, 256>>>(Ws);
    k2b_split<<<dim3(NSEQ / 32, DIM / 32, BATCH), 256>>>();
    k3_ia_stats<<<dim3(NSEQ, BATCH), 256>>>(adj, bs, outIA);
    k4_mma   <<<dim3(NSEQ / 64, BATCH), 256, 92160>>>(adj, bvec, bs, out);
    k5_gate  <<<dim3(DIM / 64, NROWS / 64), 256>>>(feat, Hw, Hb, out);
}